// round 1
// baseline (speedup 1.0000x reference)
#include <cuda_runtime.h>
#include <math.h>

#define BB 4
#define LQ 128
#define LF 64
#define NW 2
#define NFR 8
#define EE 128
#define DD 128
#define VV 64
#define WF (NW*NFR)   // 16

// ---- output layout (concatenated in reference tuple order) ----
#define OUT_FRAGCODE  0                               // (B,NW,NFR,D)   = 8192
#define OUT_QUERYCODE (BB*WF*DD)                      // (B,NW,NFR,D)   = 8192  -> off 8192
#define OUT_SELFATT   (2*BB*WF*DD)                    // (B,NW,NFR,LF)  = 4096  -> off 16384
#define OUT_GATE      (2*BB*WF*DD + BB*WF*LF)         // (B,WF,LQ)      = 8192  -> off 20480
#define OUT_QUERY     (OUT_GATE + BB*WF*LQ)           // (B,LQ,E)       = 65536 -> off 28672

// ---- scratch ----
__device__ float g_fproj[BB*WF*LF*DD];   // projected fragment (b,wf,lf,d)
__device__ float g_qatt [BB*LQ*VV];      // q_att (b,lq,v)
__device__ float g_fatt [BB*WF*LF*VV];   // f_att (b,wf,lf,v)
__device__ float g_e2   [BB*WF*LQ];      // exp(qf@val_w)*mask

// ============================================================
// Kernel A: projection (query rows then fragment rows), GEMM+bias.
// Note: the all-zero-row mask in _project is a mathematical no-op.
// ============================================================
__global__ void k_proj(const float* __restrict__ query,
                       const float* __restrict__ frag,
                       const float* __restrict__ W,
                       const float* __restrict__ bias,
                       float* __restrict__ outq) {
    int row = blockIdx.x;
    int j = threadIdx.x;      // 0..127
    __shared__ float xsh[EE];
    const float* src = (row < BB*LQ) ? (query + (size_t)row*EE)
                                     : (frag  + (size_t)(row - BB*LQ)*EE);
    xsh[j] = src[j];
    __syncthreads();
    float acc = bias[j];
    #pragma unroll 8
    for (int d = 0; d < EE; d++) acc = fmaf(xsh[d], W[d*DD + j], acc);
    float* dst = (row < BB*LQ) ? (outq + (size_t)row*DD)
                               : (g_fproj + (size_t)(row - BB*LQ)*DD);
    dst[j] = acc;
}

// ============================================================
// Kernel B: fragment self-attention softmax + frag_code
// ============================================================
__global__ void k_fragcode(const float* __restrict__ saW,
                           const float* __restrict__ fmask,
                           float* __restrict__ out) {
    int bwf = blockIdx.x;                 // 0..63  (b*WF + wf)
    int w = (bwf % WF) / NFR;
    const float* fbase = g_fproj + (size_t)bwf*LF*DD;
    __shared__ float att[LF];
    __shared__ float s_inv;
    int t = threadIdx.x;                  // 128 threads
    if (t < LF) {
        const float* fr = fbase + t*DD;
        const float* sw = saW + w*DD;
        float acc = 0.f;
        #pragma unroll 8
        for (int d = 0; d < DD; d++) acc += fr[d]*sw[d];
        att[t] = expf(acc) * fmask[bwf*LF + t];
    }
    __syncthreads();
    if (t == 0) {
        float s = 0.f;
        for (int l = 0; l < LF; l++) s += att[l];
        s_inv = 1.f / (s + 1e-7f);
    }
    __syncthreads();
    float inv = s_inv;
    if (t < LF) out[OUT_SELFATT + bwf*LF + t] = att[t]*inv;
    // frag_code[d] = sum_lf att_norm[lf] * f[lf,d]
    float acc = 0.f;
    #pragma unroll 8
    for (int l = 0; l < LF; l++) acc += att[l]*inv*fbase[l*DD + t];
    out[OUT_FRAGCODE + bwf*DD + t] = acc;
}

// ============================================================
// Kernel C: q_att = q @ q_att_W, f_att = f @ f_att_W
// ============================================================
__global__ void k_att(const float* __restrict__ outq,
                      const float* __restrict__ qW,
                      const float* __restrict__ fW) {
    int row = blockIdx.x;
    int j = threadIdx.x;      // 0..63
    __shared__ float xsh[DD];
    const float* src; const float* W; float* dst;
    if (row < BB*LQ) { src = outq + (size_t)row*DD;            W = qW; dst = g_qatt + (size_t)row*VV; }
    else             { int r = row - BB*LQ;
                       src = g_fproj + (size_t)r*DD;           W = fW; dst = g_fatt + (size_t)r*VV; }
    xsh[j] = src[j]; xsh[j+64] = src[j+64];
    __syncthreads();
    float acc = 0.f;
    #pragma unroll 8
    for (int d = 0; d < DD; d++) acc = fmaf(xsh[d], W[d*VV + j], acc);
    dst[j] = acc;
}

// ============================================================
// Kernel D (hot): per (b,wf,lq-tile32): max over lf of
//   (q_att + f_att + (q ⊙ f_lf) @ W_qf), then gate/val dots.
// 64 threads, each owns a 4(lq) x 8(v) register tile.
// ============================================================
__global__ void k_qf(const float* __restrict__ qfW,
                     const float* __restrict__ gate_w,
                     const float* __restrict__ val_w,
                     const float* __restrict__ qmask,
                     const float* __restrict__ outq,
                     float* __restrict__ out) {
    extern __shared__ float sh[];
    float* qsh    = sh;                       // 32 * 129
    float* Wsh    = sh + 32*129;              // 128 * 64
    float* fsh    = Wsh + DD*VV;              // 128
    float* fattsh = fsh + DD;                 // 64

    int blk = blockIdx.x;
    int lqt = blk & 3;
    int bwf = blk >> 2;
    int b   = bwf / WF;
    int lqbase = lqt * 32;
    int tid = threadIdx.x;                    // 0..63
    int vi  = (tid & 7) * 8;                  // v offset (8 v's)
    int l0  = (tid >> 3) * 4;                 // local lq offset (4 lq's)

    // stage W_qf (8192 floats, float4)
    {
        const float4* Wv = (const float4*)qfW;
        float4* Ws = (float4*)Wsh;
        #pragma unroll
        for (int i = tid; i < DD*VV/4; i += 64) Ws[i] = Wv[i];
    }
    // stage q tile (32 x 128), padded rows of 129
    for (int i = tid; i < 32*DD; i += 64) {
        int r = i >> 7, d = i & 127;
        qsh[r*129 + d] = outq[((size_t)(b*LQ + lqbase + r))*DD + d];
    }

    float m[4][8];
    #pragma unroll
    for (int i = 0; i < 4; i++)
        #pragma unroll
        for (int j = 0; j < 8; j++) m[i][j] = -INFINITY;

    for (int lf = 0; lf < LF; lf++) {
        __syncthreads();
        const float* fptr = g_fproj + ((size_t)bwf*LF + lf)*DD;
        fsh[tid]      = fptr[tid];
        fsh[tid + 64] = fptr[tid + 64];
        fattsh[tid]   = g_fatt[((size_t)bwf*LF + lf)*VV + tid];
        __syncthreads();

        float acc[4][8];
        #pragma unroll
        for (int i = 0; i < 4; i++)
            #pragma unroll
            for (int j = 0; j < 8; j++) acc[i][j] = 0.f;

        #pragma unroll 2
        for (int d = 0; d < DD; d++) {
            float fd = fsh[d];
            float a0 = qsh[(l0+0)*129 + d] * fd;
            float a1 = qsh[(l0+1)*129 + d] * fd;
            float a2 = qsh[(l0+2)*129 + d] * fd;
            float a3 = qsh[(l0+3)*129 + d] * fd;
            float4 w0 = *(const float4*)&Wsh[d*VV + vi];
            float4 w1 = *(const float4*)&Wsh[d*VV + vi + 4];
            acc[0][0] = fmaf(a0, w0.x, acc[0][0]); acc[0][1] = fmaf(a0, w0.y, acc[0][1]);
            acc[0][2] = fmaf(a0, w0.z, acc[0][2]); acc[0][3] = fmaf(a0, w0.w, acc[0][3]);
            acc[0][4] = fmaf(a0, w1.x, acc[0][4]); acc[0][5] = fmaf(a0, w1.y, acc[0][5]);
            acc[0][6] = fmaf(a0, w1.z, acc[0][6]); acc[0][7] = fmaf(a0, w1.w, acc[0][7]);
            acc[1][0] = fmaf(a1, w0.x, acc[1][0]); acc[1][1] = fmaf(a1, w0.y, acc[1][1]);
            acc[1][2] = fmaf(a1, w0.z, acc[1][2]); acc[1][3] = fmaf(a1, w0.w, acc[1][3]);
            acc[1][4] = fmaf(a1, w1.x, acc[1][4]); acc[1][5] = fmaf(a1, w1.y, acc[1][5]);
            acc[1][6] = fmaf(a1, w1.z, acc[1][6]); acc[1][7] = fmaf(a1, w1.w, acc[1][7]);
            acc[2][0] = fmaf(a2, w0.x, acc[2][0]); acc[2][1] = fmaf(a2, w0.y, acc[2][1]);
            acc[2][2] = fmaf(a2, w0.z, acc[2][2]); acc[2][3] = fmaf(a2, w0.w, acc[2][3]);
            acc[2][4] = fmaf(a2, w1.x, acc[2][4]); acc[2][5] = fmaf(a2, w1.y, acc[2][5]);
            acc[2][6] = fmaf(a2, w1.z, acc[2][6]); acc[2][7] = fmaf(a2, w1.w, acc[2][7]);
            acc[3][0] = fmaf(a3, w0.x, acc[3][0]); acc[3][1] = fmaf(a3, w0.y, acc[3][1]);
            acc[3][2] = fmaf(a3, w0.z, acc[3][2]); acc[3][3] = fmaf(a3, w0.w, acc[3][3]);
            acc[3][4] = fmaf(a3, w1.x, acc[3][4]); acc[3][5] = fmaf(a3, w1.y, acc[3][5]);
            acc[3][6] = fmaf(a3, w1.z, acc[3][6]); acc[3][7] = fmaf(a3, w1.w, acc[3][7]);
        }
        #pragma unroll
        for (int i = 0; i < 4; i++)
            #pragma unroll
            for (int j = 0; j < 8; j++)
                m[i][j] = fmaxf(m[i][j], acc[i][j] + fattsh[vi + j]);
    }

    // add q_att, fold gate/val dots, reduce across the 8 v-lanes per lq row
    #pragma unroll
    for (int i = 0; i < 4; i++) {
        int lq = lqbase + l0 + i;
        float gs = 0.f, vs = 0.f;
        #pragma unroll
        for (int j = 0; j < 8; j++) {
            float val = m[i][j] + g_qatt[((size_t)(b*LQ + lq))*VV + vi + j];
            gs += val * gate_w[vi + j];
            vs += val * val_w[vi + j];
        }
        #pragma unroll
        for (int off = 4; off >= 1; off >>= 1) {
            gs += __shfl_down_sync(0xffffffffu, gs, off, 8);
            vs += __shfl_down_sync(0xffffffffu, vs, off, 8);
        }
        if ((tid & 7) == 0) {
            float qm = qmask[b*LQ + lq];
            out[OUT_GATE + bwf*LQ + lq] = (1.f / (1.f + expf(-gs))) * qm;
            g_e2[bwf*LQ + lq] = expf(vs) * qm;
        }
    }
}

// ============================================================
// Kernel E: normalize e2 over LQ, query_code = sum_lq norm*q
// ============================================================
__global__ void k_qcode(const float* __restrict__ outq,
                        float* __restrict__ out) {
    int bwf = blockIdx.x;       // 0..63
    int b = bwf / WF;
    int t = threadIdx.x;        // 0..127 (d)
    __shared__ float esh[LQ];
    __shared__ float s_inv;
    esh[t] = g_e2[bwf*LQ + t];
    __syncthreads();
    if (t == 0) {
        float s = 0.f;
        for (int l = 0; l < LQ; l++) s += esh[l];
        s_inv = 1.f / (s + 1e-7f);
    }
    __syncthreads();
    float inv = s_inv;
    float acc = 0.f;
    #pragma unroll 8
    for (int l = 0; l < LQ; l++) acc += esh[l] * outq[((size_t)(b*LQ + l))*DD + t];
    out[OUT_QUERYCODE + bwf*DD + t] = acc * inv;
}

// ============================================================
extern "C" void kernel_launch(void* const* d_in, const int* in_sizes, int n_in,
                              void* d_out, int out_size) {
    const float* query    = (const float*)d_in[0];
    const float* fragment = (const float*)d_in[1];
    const float* qmask    = (const float*)d_in[2];
    const float* fmask    = (const float*)d_in[3];
    const float* projW    = (const float*)d_in[4];
    const float* projb    = (const float*)d_in[5];
    const float* saW      = (const float*)d_in[6];
    const float* qattW    = (const float*)d_in[7];
    const float* fattW    = (const float*)d_in[8];
    const float* qfW      = (const float*)d_in[9];
    const float* gatew    = (const float*)d_in[10];
    const float* valw     = (const float*)d_in[11];
    float* out = (float*)d_out;

    const int nrows = BB*LQ + BB*WF*LF;   // 4608

    k_proj<<<nrows, 128>>>(query, fragment, projW, projb, out + OUT_QUERY);
    k_fragcode<<<BB*WF, 128>>>(saW, fmask, out);
    k_att<<<nrows, 64>>>(out + OUT_QUERY, qattW, fattW);

    const int smem = (32*129 + DD*VV + DD + VV) * (int)sizeof(float);  // 50048 B
    cudaFuncSetAttribute(k_qf, cudaFuncAttributeMaxDynamicSharedMemorySize, smem);
    k_qf<<<BB*WF*4, 64, smem>>>(qfW, gatew, valw, qmask, out + OUT_QUERY, out);

    k_qcode<<<BB*WF, 128>>>(out + OUT_QUERY, out);
}